// round 8
// baseline (speedup 1.0000x reference)
#include <cuda_runtime.h>
#include <math.h>
#include <stdint.h>

#define BB 16
#define CC 256
#define NN 4096
#define HH 8
#define DD 64
#define HID 512
#define THID 1536
#define NSPLIT 8
#define SCALE 0.125f
#define SQRTC 16.0f

// ---------------- scratch ----------------
__device__ float g_qkv[(size_t)BB * THID * NN];   // q [0,512), k [512,1024), v [1024,1536)
__device__ float g_wt[(size_t)CC * THID];         // w_qkv^T [k=256][m=1536]
__device__ float g_ctxp[(size_t)NSPLIT * BB * HH * DD * DD];
__device__ float g_sump[(size_t)NSPLIT * BB * HID];
__device__ float g_ctx[(size_t)BB * HH * DD * DD];
__device__ float g_At[(size_t)BB * HID * CC];     // A^T: [b][hd=512][c=256]

// ---------------- helpers ----------------
__device__ __forceinline__ uint32_t packh(float lo, float hi) {
    uint32_t r;
    asm("cvt.rn.f16x2.f32 %0, %1, %2;" : "=r"(r) : "f"(hi), "f"(lo));
    return r;
}
#define CP16(sm, gp) asm volatile("cp.async.cg.shared.global [%0], [%1], 16;" :: "r"(sm), "l"(gp))
#define CP_COMMIT() asm volatile("cp.async.commit_group;")
#define CP_WAIT1() asm volatile("cp.async.wait_group 1;")
#define CP_WAIT0() asm volatile("cp.async.wait_group 0;")

// m16n8k16 fp16 mma, f32 accumulate
__device__ __forceinline__ void mma_f16(float* c, const uint32_t* a, const uint32_t* b) {
    asm volatile(
        "mma.sync.aligned.m16n8k16.row.col.f32.f16.f16.f32 "
        "{%0,%1,%2,%3}, {%4,%5,%6,%7}, {%8,%9}, {%0,%1,%2,%3};"
        : "+f"(c[0]), "+f"(c[1]), "+f"(c[2]), "+f"(c[3])
        : "r"(a[0]), "r"(a[1]), "r"(a[2]), "r"(a[3]), "r"(b[0]), "r"(b[1]));
}

// ---------------- K0: transpose w_qkv [1536x256] -> g_wt [256x1536] ----------------
__global__ __launch_bounds__(256) void k_wt(const float* __restrict__ w) {
    __shared__ float tl[32][33];
    int k0 = blockIdx.x * 32, m0 = blockIdx.y * 32;
    int tx = threadIdx.x, ty = threadIdx.y;
#pragma unroll
    for (int i = 0; i < 4; i++)
        tl[ty + i * 8][tx] = w[(size_t)(m0 + ty + i * 8) * CC + k0 + tx];
    __syncthreads();
#pragma unroll
    for (int i = 0; i < 4; i++)
        g_wt[(size_t)(k0 + ty + i * 8) * THID + m0 + tx] = tl[tx][ty + i * 8];
}

// ---------------- K1: qkv = w_qkv @ x (fp16 mma, 128x128 tiles) ----------------
__global__ __launch_bounds__(256) void k_qkv(const float* __restrict__ x,
                                             float* __restrict__ Cdst) {
    __shared__ float As[2][16][136];
    __shared__ float Bs[2][16][136];

    const int t = threadIdx.x;
    const int b = blockIdx.z;
    const int m0 = blockIdx.y * 128;
    const int n0 = blockIdx.x * 128;

    const float* Ab = g_wt;
    const float* Bb = x + (size_t)b * CC * NN;
    float* Cb = Cdst + (size_t)b * THID * NN;

    const int id0 = t, id1 = t + 256;
    const int ar0 = id0 >> 5, ac0 = (id0 & 31) * 4;
    const int ar1 = id1 >> 5, ac1 = (id1 & 31) * 4;
    unsigned sA0[2], sA1[2], sB0[2], sB1[2];
#pragma unroll
    for (int s = 0; s < 2; s++) {
        sA0[s] = (unsigned)__cvta_generic_to_shared(&As[s][ar0][ac0]);
        sA1[s] = (unsigned)__cvta_generic_to_shared(&As[s][ar1][ac1]);
        sB0[s] = (unsigned)__cvta_generic_to_shared(&Bs[s][ar0][ac0]);
        sB1[s] = (unsigned)__cvta_generic_to_shared(&Bs[s][ar1][ac1]);
    }

    const int wid = t >> 5, lane = t & 31;
    const int wm = (wid >> 2) * 64;
    const int wn = (wid & 3) * 32;
    const int g = lane >> 2, t4 = lane & 3;

    float acc[4][4][4];
#pragma unroll
    for (int mt = 0; mt < 4; mt++)
#pragma unroll
        for (int nt = 0; nt < 4; nt++)
#pragma unroll
            for (int r = 0; r < 4; r++) acc[mt][nt][r] = 0.f;

    const int NK = CC / 16;
    CP16(sA0[0], Ab + (size_t)ar0 * THID + m0 + ac0);
    CP16(sA1[0], Ab + (size_t)ar1 * THID + m0 + ac1);
    CP16(sB0[0], Bb + (size_t)ar0 * NN + n0 + ac0);
    CP16(sB1[0], Bb + (size_t)ar1 * NN + n0 + ac1);
    CP_COMMIT();

    for (int kt = 0; kt < NK; kt++) {
        if (kt + 1 < NK) {
            const int k0 = (kt + 1) * 16;
            const int buf = (kt + 1) & 1;
            CP16(sA0[buf], Ab + (size_t)(k0 + ar0) * THID + m0 + ac0);
            CP16(sA1[buf], Ab + (size_t)(k0 + ar1) * THID + m0 + ac1);
            CP16(sB0[buf], Bb + (size_t)(k0 + ar0) * NN + n0 + ac0);
            CP16(sB1[buf], Bb + (size_t)(k0 + ar1) * NN + n0 + ac1);
            CP_COMMIT();
            CP_WAIT1();
        } else {
            CP_WAIT0();
        }
        __syncthreads();
        const int buf = kt & 1;
        // one m16n8k16 step covers the full 16-deep stage
        uint32_t a[4][4], bf[4][2];
#pragma unroll
        for (int mt = 0; mt < 4; mt++) {
            int mr = wm + mt * 16 + g;
            a[mt][0] = packh(As[buf][2 * t4][mr],     As[buf][2 * t4 + 1][mr]);
            a[mt][1] = packh(As[buf][2 * t4][mr + 8], As[buf][2 * t4 + 1][mr + 8]);
            a[mt][2] = packh(As[buf][2 * t4 + 8][mr],     As[buf][2 * t4 + 9][mr]);
            a[mt][3] = packh(As[buf][2 * t4 + 8][mr + 8], As[buf][2 * t4 + 9][mr + 8]);
        }
#pragma unroll
        for (int nt = 0; nt < 4; nt++) {
            int nc = wn + nt * 8 + g;
            bf[nt][0] = packh(Bs[buf][2 * t4][nc],     Bs[buf][2 * t4 + 1][nc]);
            bf[nt][1] = packh(Bs[buf][2 * t4 + 8][nc], Bs[buf][2 * t4 + 9][nc]);
        }
#pragma unroll
        for (int mt = 0; mt < 4; mt++)
#pragma unroll
            for (int nt = 0; nt < 4; nt++) mma_f16(acc[mt][nt], a[mt], bf[nt]);
        __syncthreads();
    }
#pragma unroll
    for (int mt = 0; mt < 4; mt++) {
        int row = m0 + wm + mt * 16 + g;
#pragma unroll
        for (int nt = 0; nt < 4; nt++) {
            int col = n0 + wn + nt * 8 + 2 * t4;
            *(float2*)(Cb + (size_t)row * NN + col) = make_float2(acc[mt][nt][0], acc[mt][nt][1]);
            *(float2*)(Cb + (size_t)(row + 8) * NN + col) = make_float2(acc[mt][nt][2], acc[mt][nt][3]);
        }
    }
}

// ---------------- K2: context partials via fp16 mma + fused exp-sum ----------------
__global__ __launch_bounds__(128) void k_context() {
    __shared__ float Ks[64][36];
    __shared__ float Vs[64][36];
    int t = threadIdx.x;
    int sp = blockIdx.x, h = blockIdx.y, b = blockIdx.z;
    const float* kg = g_qkv + ((size_t)b * THID + HID + h * 64) * NN + sp * 512;
    const float* vg = g_qkv + ((size_t)b * THID + 2 * HID + h * 64) * NN + sp * 512;
    int wid = t >> 5, lane = t & 31;
    int g = lane >> 2, t4 = lane & 3;
    int wm = wid * 16;
    int lrow = t >> 3, lcol = (t & 7) * 4;

    float acc[8][4];
#pragma unroll
    for (int nt = 0; nt < 8; nt++)
#pragma unroll
        for (int r = 0; r < 4; r++) acc[nt][r] = 0.f;
    float esum[4] = {0.f, 0.f, 0.f, 0.f};

    for (int c0 = 0; c0 < 512; c0 += 32) {
        __syncthreads();
#pragma unroll
        for (int i = 0; i < 4; i++) {
            int row = lrow + 16 * i;
            float4 kf = *(const float4*)(kg + (size_t)row * NN + c0 + lcol);
            float e0 = __expf(kf.x), e1 = __expf(kf.y), e2 = __expf(kf.z), e3 = __expf(kf.w);
            Ks[row][lcol] = e0; Ks[row][lcol + 1] = e1;
            Ks[row][lcol + 2] = e2; Ks[row][lcol + 3] = e3;
            esum[i] += e0 + e1 + e2 + e3;
            float4 vf = *(const float4*)(vg + (size_t)row * NN + c0 + lcol);
            *(float4*)&Vs[row][lcol] = vf;
        }
        __syncthreads();
        // Ks/Vs are [row][k] (m-major): consecutive k contiguous -> direct packs
#pragma unroll
        for (int kk = 0; kk < 32; kk += 16) {
            uint32_t a[4], bf[2];
            a[0] = packh(Ks[wm + g][kk + 2 * t4],     Ks[wm + g][kk + 2 * t4 + 1]);
            a[1] = packh(Ks[wm + 8 + g][kk + 2 * t4], Ks[wm + 8 + g][kk + 2 * t4 + 1]);
            a[2] = packh(Ks[wm + g][kk + 2 * t4 + 8],     Ks[wm + g][kk + 2 * t4 + 9]);
            a[3] = packh(Ks[wm + 8 + g][kk + 2 * t4 + 8], Ks[wm + 8 + g][kk + 2 * t4 + 9]);
#pragma unroll
            for (int nt = 0; nt < 8; nt++) {
                bf[0] = packh(Vs[nt * 8 + g][kk + 2 * t4],     Vs[nt * 8 + g][kk + 2 * t4 + 1]);
                bf[1] = packh(Vs[nt * 8 + g][kk + 2 * t4 + 8], Vs[nt * 8 + g][kk + 2 * t4 + 9]);
                mma_f16(acc[nt], a, bf);
            }
        }
    }
#pragma unroll
    for (int i = 0; i < 4; i++) {
#pragma unroll
        for (int o = 1; o < 8; o <<= 1) esum[i] += __shfl_xor_sync(0xffffffffu, esum[i], o);
    }
    if ((lane & 7) == 0) {
        float* sp_out = g_sump + ((size_t)sp * BB + b) * HID + h * 64;
#pragma unroll
        for (int i = 0; i < 4; i++) sp_out[lrow + 16 * i] = esum[i];
    }
    float* op = g_ctxp + (((size_t)sp * BB + b) * HH + h) * (DD * DD);
#pragma unroll
    for (int nt = 0; nt < 8; nt++) {
        int col = nt * 8 + 2 * t4;
        *(float2*)(op + (wm + g) * DD + col) = make_float2(acc[nt][0], acc[nt][1]);
        *(float2*)(op + (wm + 8 + g) * DD + col) = make_float2(acc[nt][2], acc[nt][3]);
    }
}

// ---------------- K3: reduce partials, divide by exp-sum ----------------
__global__ __launch_bounds__(256) void k_ctxred() {
    int idx = blockIdx.x * 256 + threadIdx.x;
    float s = 0.f;
#pragma unroll
    for (int p = 0; p < NSPLIT; p++) s += g_ctxp[(size_t)p * (BB * HH * DD * DD) + idx];
    int d = (idx >> 6) & 63;
    int h = (idx >> 12) & 7;
    int b = idx >> 15;
    float den = 0.f;
#pragma unroll
    for (int p = 0; p < NSPLIT; p++) den += g_sump[((size_t)p * BB + b) * HID + h * 64 + d];
    g_ctx[idx] = s / den;
}

// ---------------- K4: A^T[b][hd][c] = sum_e wout[c][h64+e]*ctx[d][e] ----------------
__global__ __launch_bounds__(128) void k_Agemm(const float* __restrict__ wout) {
    __shared__ float Wouts[128][64];
    __shared__ float ctxs[64][64];
    int t = threadIdx.x;
    int cseg = blockIdx.x, h = blockIdx.y, b = blockIdx.z;
    int cbase = cseg * 128;
#pragma unroll
    for (int i = 0; i < 16; i++) {
        int lin4 = t + i * 128;
        int c = lin4 >> 4, e4 = lin4 & 15;
        *(float4*)&Wouts[c][e4 * 4] = *(const float4*)(wout + (size_t)(cbase + c) * HID + h * 64 + e4 * 4);
    }
    const float* ctxg = g_ctx + ((size_t)b * HH + h) * DD * DD;
#pragma unroll
    for (int i = 0; i < 8; i++) {
        int lin4 = t + i * 128;
        int d = lin4 >> 4, e4 = lin4 & 15;
        *(float4*)&ctxs[d][e4 * 4] = *(const float4*)(ctxg + d * 64 + e4 * 4);
    }
    __syncthreads();
    float acc[64];
#pragma unroll
    for (int d = 0; d < 64; d++) acc[d] = 0.f;
    for (int e = 0; e < 64; e++) {
        float w = Wouts[t][e];
#pragma unroll
        for (int d = 0; d < 64; d++) acc[d] = fmaf(w, ctxs[d][e], acc[d]);
    }
    float* op = g_At + ((size_t)b * HID + h * 64) * CC + cbase + t;
    for (int d = 0; d < 64; d++) op[(size_t)d * CC] = acc[d];
}

// ---------------- K5: fused q-softmax + output GEMM + bias + RMSNorm ----------------
__global__ __launch_bounds__(256) void k_out(const float* __restrict__ bo,
                                             const float* __restrict__ gn,
                                             float* __restrict__ y) {
    __shared__ float Qs[64][72];
    __shared__ float As[16][264];
    __shared__ float redM[4][64];
    __shared__ float redS[4][64];
    __shared__ float colM[64];
    __shared__ float colS[64];
    __shared__ float sred[64][4];
    __shared__ float cscale[64];

    int t = threadIdx.x;
    int b = blockIdx.y, n0 = blockIdx.x * 64;
    int wid = t >> 5, lane = t & 31;
    int g = lane >> 2, t4 = lane & 3;
    int wm = (wid >> 1) * 64, wn = (wid & 1) * 32;
    int part = t >> 6, col = t & 63;

    float acc[4][4][4];
#pragma unroll
    for (int mt = 0; mt < 4; mt++)
#pragma unroll
        for (int nt = 0; nt < 4; nt++)
#pragma unroll
            for (int r = 0; r < 4; r++) acc[mt][nt][r] = 0.f;

    for (int h = 0; h < 8; h++) {
        __syncthreads();
#pragma unroll
        for (int i = 0; i < 4; i++) {
            int lin4 = t + i * 256;
            int row = lin4 >> 4, c4 = (lin4 & 15) * 4;
            *(float4*)&Qs[row][c4] =
                *(const float4*)(g_qkv + ((size_t)b * THID + h * 64 + row) * NN + n0 + c4);
        }
        __syncthreads();
        float lm = -1e30f;
#pragma unroll
        for (int r = 0; r < 16; r++) lm = fmaxf(lm, Qs[part * 16 + r][col]);
        redM[part][col] = lm;
        __syncthreads();
        float M = fmaxf(fmaxf(redM[0][col], redM[1][col]), fmaxf(redM[2][col], redM[3][col]));
        float ls = 0.f;
#pragma unroll
        for (int r = 0; r < 16; r++) ls += __expf(Qs[part * 16 + r][col] - M);
        redS[part][col] = ls;
        __syncthreads();
        if (t < 64) {
            colM[t] = M;
            colS[t] = SCALE / (redS[0][t] + redS[1][t] + redS[2][t] + redS[3][t]);
        }
        __syncthreads();
#pragma unroll
        for (int i = 0; i < 16; i++) {
            int lin = t + i * 256;
            int d = lin >> 6, n = lin & 63;
            Qs[d][n] = __expf(Qs[d][n] - colM[n]) * colS[n];
        }
        for (int dc = 0; dc < 4; dc++) {
            __syncthreads();
#pragma unroll
            for (int i = 0; i < 4; i++) {
                int lin4 = t + i * 256;
                int row = lin4 >> 6, c4 = (lin4 & 63) * 4;
                *(float4*)&As[row][c4] =
                    *(const float4*)(g_At + ((size_t)b * HID + h * 64 + dc * 16 + row) * CC + c4);
            }
            __syncthreads();
            // one m16n8k16 step per 16-deep chunk
            uint32_t a[4][4], bf[4][2];
#pragma unroll
            for (int mt = 0; mt < 4; mt++) {
                int mr = wm + mt * 16 + g;
                a[mt][0] = packh(As[2 * t4][mr],     As[2 * t4 + 1][mr]);
                a[mt][1] = packh(As[2 * t4][mr + 8], As[2 * t4 + 1][mr + 8]);
                a[mt][2] = packh(As[2 * t4 + 8][mr],     As[2 * t4 + 9][mr]);
                a[mt][3] = packh(As[2 * t4 + 8][mr + 8], As[2 * t4 + 9][mr + 8]);
            }
#pragma unroll
            for (int nt = 0; nt < 4; nt++) {
                int nc = wn + nt * 8 + g;
                bf[nt][0] = packh(Qs[dc * 16 + 2 * t4][nc],     Qs[dc * 16 + 2 * t4 + 1][nc]);
                bf[nt][1] = packh(Qs[dc * 16 + 2 * t4 + 8][nc], Qs[dc * 16 + 2 * t4 + 9][nc]);
            }
#pragma unroll
            for (int mt = 0; mt < 4; mt++)
#pragma unroll
                for (int nt = 0; nt < 4; nt++) mma_f16(acc[mt][nt], a[mt], bf[nt]);
        }
    }
    float ps[4][2];
#pragma unroll
    for (int nt = 0; nt < 4; nt++) { ps[nt][0] = 0.f; ps[nt][1] = 0.f; }
#pragma unroll
    for (int mt = 0; mt < 4; mt++) {
        int row = wm + mt * 16 + g;
        float b0v = bo[row], b1v = bo[row + 8];
#pragma unroll
        for (int nt = 0; nt < 4; nt++) {
            acc[mt][nt][0] += b0v;
            acc[mt][nt][1] += b0v;
            acc[mt][nt][2] += b1v;
            acc[mt][nt][3] += b1v;
            ps[nt][0] += acc[mt][nt][0] * acc[mt][nt][0] + acc[mt][nt][2] * acc[mt][nt][2];
            ps[nt][1] += acc[mt][nt][1] * acc[mt][nt][1] + acc[mt][nt][3] * acc[mt][nt][3];
        }
    }
#pragma unroll
    for (int nt = 0; nt < 4; nt++)
#pragma unroll
        for (int j = 0; j < 2; j++) {
#pragma unroll
            for (int o = 4; o <= 16; o <<= 1)
                ps[nt][j] += __shfl_xor_sync(0xffffffffu, ps[nt][j], o);
        }
    if (g == 0) {
#pragma unroll
        for (int nt = 0; nt < 4; nt++)
#pragma unroll
            for (int j = 0; j < 2; j++)
                sred[wn + nt * 8 + 2 * t4 + j][wid >> 1] = ps[nt][j];
    }
    __syncthreads();
    if (t < 64) {
        float tot = sred[t][0] + sred[t][1] + sred[t][2] + sred[t][3];
        cscale[t] = SQRTC / fmaxf(sqrtf(tot), 1e-12f);
    }
    __syncthreads();
#pragma unroll
    for (int mt = 0; mt < 4; mt++) {
        int row = wm + mt * 16 + g;
        float g0 = gn[row], g1 = gn[row + 8];
#pragma unroll
        for (int nt = 0; nt < 4; nt++) {
            int c = wn + nt * 8 + 2 * t4;
            float s0 = cscale[c], s1 = cscale[c + 1];
            *(float2*)(y + ((size_t)b * CC + row) * NN + n0 + c) =
                make_float2(acc[mt][nt][0] * s0 * g0, acc[mt][nt][1] * s1 * g0);
            *(float2*)(y + ((size_t)b * CC + row + 8) * NN + n0 + c) =
                make_float2(acc[mt][nt][2] * s0 * g1, acc[mt][nt][3] * s1 * g1);
        }
    }
}

// ---------------- launch ----------------
extern "C" void kernel_launch(void* const* d_in, const int* in_sizes, int n_in,
                              void* d_out, int out_size) {
    const float* x      = (const float*)d_in[0];
    const float* w_qkv  = (const float*)d_in[1];
    const float* w_out  = (const float*)d_in[2];
    const float* b_out  = (const float*)d_in[3];
    const float* g_norm = (const float*)d_in[4];
    float* y = (float*)d_out;

    float* qkv_ptr = nullptr;
    cudaGetSymbolAddress((void**)&qkv_ptr, g_qkv);

    k_wt<<<dim3(CC / 32, THID / 32), dim3(32, 8)>>>(w_qkv);
    k_qkv<<<dim3(NN / 128, THID / 128, BB), 256>>>(x, qkv_ptr);
    k_context<<<dim3(NSPLIT, HH, BB), 128>>>();
    k_ctxred<<<(BB * HH * DD * DD) / 256, 256>>>();
    k_Agemm<<<dim3(2, HH, BB), 128>>>(w_out);
    k_out<<<dim3(NN / 64, BB), 256>>>(b_out, g_norm, y);
}

// round 11
// speedup vs baseline: 1.1153x; 1.1153x over previous
#include <cuda_runtime.h>
#include <cuda_fp16.h>
#include <math.h>
#include <stdint.h>

#define BB 16
#define CC 256
#define NN 4096
#define HH 8
#define DD 64
#define HID 512
#define THID 1536
#define NSPLIT 8
#define SCALE 0.125f
#define SQRTC 16.0f

// ---------------- scratch ----------------
__device__ __half g_qkvh[(size_t)BB * THID * NN];  // fp16: q [0,512), k [512,1024), v [1024,1536)
__device__ float g_wt[(size_t)CC * THID];          // w_qkv^T [k=256][m=1536] fp32
__device__ float g_ctxp[(size_t)NSPLIT * BB * HH * DD * DD];
__device__ float g_sump[(size_t)NSPLIT * BB * HID];
__device__ float g_ctx[(size_t)BB * HH * DD * DD];
__device__ __half g_Ath[(size_t)BB * HID * CC];    // A^T fp16: [b][hd=512][c=256]

// ---------------- helpers ----------------
__device__ __forceinline__ uint32_t f2tf32(float x) {
    uint32_t u;
    asm("cvt.rna.tf32.f32 %0, %1;" : "=r"(u) : "f"(x));
    return u;
}
__device__ __forceinline__ uint32_t packh(float lo, float hi) {
    uint32_t r;
    asm("cvt.rn.f16x2.f32 %0, %1, %2;" : "=r"(r) : "f"(hi), "f"(lo));
    return r;
}
#define CP16(sm, gp) asm volatile("cp.async.cg.shared.global [%0], [%1], 16;" :: "r"(sm), "l"(gp))
#define CP_COMMIT() asm volatile("cp.async.commit_group;")
#define CP_WAIT1() asm volatile("cp.async.wait_group 1;")
#define CP_WAIT0() asm volatile("cp.async.wait_group 0;")

__device__ __forceinline__ void mma_tf32(float* c, const uint32_t* a, const uint32_t* b) {
    asm volatile(
        "mma.sync.aligned.m16n8k8.row.col.f32.tf32.tf32.f32 "
        "{%0,%1,%2,%3}, {%4,%5,%6,%7}, {%8,%9}, {%0,%1,%2,%3};"
        : "+f"(c[0]), "+f"(c[1]), "+f"(c[2]), "+f"(c[3])
        : "r"(a[0]), "r"(a[1]), "r"(a[2]), "r"(a[3]), "r"(b[0]), "r"(b[1]));
}

// load 4 halves -> 4 floats
__device__ __forceinline__ void ld4h(const __half* p, float* f) {
    uint2 raw = *(const uint2*)p;
    float2 lo = __half22float2(*(__half2*)&raw.x);
    float2 hi = __half22float2(*(__half2*)&raw.y);
    f[0] = lo.x; f[1] = lo.y; f[2] = hi.x; f[3] = hi.y;
}

// ---------------- K0: transpose w_qkv [1536x256] -> g_wt [256x1536] ----------------
__global__ __launch_bounds__(256) void k_wt(const float* __restrict__ w) {
    __shared__ float tl[32][33];
    int k0 = blockIdx.x * 32, m0 = blockIdx.y * 32;
    int tx = threadIdx.x, ty = threadIdx.y;
#pragma unroll
    for (int i = 0; i < 4; i++)
        tl[ty + i * 8][tx] = w[(size_t)(m0 + ty + i * 8) * CC + k0 + tx];
    __syncthreads();
#pragma unroll
    for (int i = 0; i < 4; i++)
        g_wt[(size_t)(k0 + ty + i * 8) * THID + m0 + tx] = tl[tx][ty + i * 8];
}

// ---------------- K1: qkv = w_qkv @ x (tf32 mma, 128x128 tiles, fp16 output) ----------------
__global__ __launch_bounds__(256) void k_qkv(const float* __restrict__ x) {
    __shared__ float As[2][16][136];
    __shared__ float Bs[2][16][136];

    const int t = threadIdx.x;
    const int b = blockIdx.z;
    const int m0 = blockIdx.y * 128;
    const int n0 = blockIdx.x * 128;

    const float* Ab = g_wt;
    const float* Bb = x + (size_t)b * CC * NN;
    __half* Cb = g_qkvh + (size_t)b * THID * NN;

    const int id0 = t, id1 = t + 256;
    const int ar0 = id0 >> 5, ac0 = (id0 & 31) * 4;
    const int ar1 = id1 >> 5, ac1 = (id1 & 31) * 4;
    unsigned sA0[2], sA1[2], sB0[2], sB1[2];
#pragma unroll
    for (int s = 0; s < 2; s++) {
        sA0[s] = (unsigned)__cvta_generic_to_shared(&As[s][ar0][ac0]);
        sA1[s] = (unsigned)__cvta_generic_to_shared(&As[s][ar1][ac1]);
        sB0[s] = (unsigned)__cvta_generic_to_shared(&Bs[s][ar0][ac0]);
        sB1[s] = (unsigned)__cvta_generic_to_shared(&Bs[s][ar1][ac1]);
    }

    const int wid = t >> 5, lane = t & 31;
    const int wm = (wid >> 2) * 64;
    const int wn = (wid & 3) * 32;
    const int g = lane >> 2, t4 = lane & 3;

    float acc[4][4][4];
#pragma unroll
    for (int mt = 0; mt < 4; mt++)
#pragma unroll
        for (int nt = 0; nt < 4; nt++)
#pragma unroll
            for (int r = 0; r < 4; r++) acc[mt][nt][r] = 0.f;

    const int NK = CC / 16;
    CP16(sA0[0], Ab + (size_t)ar0 * THID + m0 + ac0);
    CP16(sA1[0], Ab + (size_t)ar1 * THID + m0 + ac1);
    CP16(sB0[0], Bb + (size_t)ar0 * NN + n0 + ac0);
    CP16(sB1[0], Bb + (size_t)ar1 * NN + n0 + ac1);
    CP_COMMIT();

    for (int kt = 0; kt < NK; kt++) {
        if (kt + 1 < NK) {
            const int k0 = (kt + 1) * 16;
            const int buf = (kt + 1) & 1;
            CP16(sA0[buf], Ab + (size_t)(k0 + ar0) * THID + m0 + ac0);
            CP16(sA1[buf], Ab + (size_t)(k0 + ar1) * THID + m0 + ac1);
            CP16(sB0[buf], Bb + (size_t)(k0 + ar0) * NN + n0 + ac0);
            CP16(sB1[buf], Bb + (size_t)(k0 + ar1) * NN + n0 + ac1);
            CP_COMMIT();
            CP_WAIT1();
        } else {
            CP_WAIT0();
        }
        __syncthreads();
        const int buf = kt & 1;
#pragma unroll
        for (int kk = 0; kk < 16; kk += 8) {
            uint32_t a[4][4], bf[4][2];
#pragma unroll
            for (int mt = 0; mt < 4; mt++) {
                int mr = wm + mt * 16 + g;
                a[mt][0] = f2tf32(As[buf][kk + t4][mr]);
                a[mt][1] = f2tf32(As[buf][kk + t4][mr + 8]);
                a[mt][2] = f2tf32(As[buf][kk + t4 + 4][mr]);
                a[mt][3] = f2tf32(As[buf][kk + t4 + 4][mr + 8]);
            }
#pragma unroll
            for (int nt = 0; nt < 4; nt++) {
                int nc = wn + nt * 8 + g;
                bf[nt][0] = f2tf32(Bs[buf][kk + t4][nc]);
                bf[nt][1] = f2tf32(Bs[buf][kk + t4 + 4][nc]);
            }
#pragma unroll
            for (int mt = 0; mt < 4; mt++)
#pragma unroll
                for (int nt = 0; nt < 4; nt++) mma_tf32(acc[mt][nt], a[mt], bf[nt]);
        }
        __syncthreads();
    }
    // fp16 epilogue: each (row, col) pair holds 2 consecutive n
#pragma unroll
    for (int mt = 0; mt < 4; mt++) {
        int row = m0 + wm + mt * 16 + g;
#pragma unroll
        for (int nt = 0; nt < 4; nt++) {
            int col = n0 + wn + nt * 8 + 2 * t4;
            *(uint32_t*)(Cb + (size_t)row * NN + col) = packh(acc[mt][nt][0], acc[mt][nt][1]);
            *(uint32_t*)(Cb + (size_t)(row + 8) * NN + col) = packh(acc[mt][nt][2], acc[mt][nt][3]);
        }
    }
}

// ---------------- K2: context partials via tf32 mma + fused exp-sum (fp16 input) ----------------
__global__ __launch_bounds__(128) void k_context() {
    __shared__ float Ks[64][36];
    __shared__ float Vs[64][36];
    int t = threadIdx.x;
    int sp = blockIdx.x, h = blockIdx.y, b = blockIdx.z;
    const __half* kg = g_qkvh + ((size_t)b * THID + HID + h * 64) * NN + sp * 512;
    const __half* vg = g_qkvh + ((size_t)b * THID + 2 * HID + h * 64) * NN + sp * 512;
    int wid = t >> 5, lane = t & 31;
    int g = lane >> 2, t4 = lane & 3;
    int wm = wid * 16;
    int lrow = t >> 3, lcol = (t & 7) * 4;

    float acc[8][4];
#pragma unroll
    for (int nt = 0; nt < 8; nt++)
#pragma unroll
        for (int r = 0; r < 4; r++) acc[nt][r] = 0.f;
    float esum[4] = {0.f, 0.f, 0.f, 0.f};

    for (int c0 = 0; c0 < 512; c0 += 32) {
        __syncthreads();
#pragma unroll
        for (int i = 0; i < 4; i++) {
            int row = lrow + 16 * i;
            float kf[4];
            ld4h(kg + (size_t)row * NN + c0 + lcol, kf);
            float e0 = __expf(kf[0]), e1 = __expf(kf[1]), e2 = __expf(kf[2]), e3 = __expf(kf[3]);
            Ks[row][lcol] = e0; Ks[row][lcol + 1] = e1;
            Ks[row][lcol + 2] = e2; Ks[row][lcol + 3] = e3;
            esum[i] += e0 + e1 + e2 + e3;
            float vf[4];
            ld4h(vg + (size_t)row * NN + c0 + lcol, vf);
            Vs[row][lcol] = vf[0]; Vs[row][lcol + 1] = vf[1];
            Vs[row][lcol + 2] = vf[2]; Vs[row][lcol + 3] = vf[3];
        }
        __syncthreads();
#pragma unroll
        for (int kk = 0; kk < 32; kk += 8) {
            uint32_t a[4], bf[2];
            a[0] = f2tf32(Ks[wm + g][kk + t4]);
            a[1] = f2tf32(Ks[wm + 8 + g][kk + t4]);
            a[2] = f2tf32(Ks[wm + g][kk + t4 + 4]);
            a[3] = f2tf32(Ks[wm + 8 + g][kk + t4 + 4]);
#pragma unroll
            for (int nt = 0; nt < 8; nt++) {
                bf[0] = f2tf32(Vs[nt * 8 + g][kk + t4]);
                bf[1] = f2tf32(Vs[nt * 8 + g][kk + t4 + 4]);
                mma_tf32(acc[nt], a, bf);
            }
        }
    }
#pragma unroll
    for (int i = 0; i < 4; i++) {
#pragma unroll
        for (int o = 1; o < 8; o <<= 1) esum[i] += __shfl_xor_sync(0xffffffffu, esum[i], o);
    }
    if ((lane & 7) == 0) {
        float* sp_out = g_sump + ((size_t)sp * BB + b) * HID + h * 64;
#pragma unroll
        for (int i = 0; i < 4; i++) sp_out[lrow + 16 * i] = esum[i];
    }
    float* op = g_ctxp + (((size_t)sp * BB + b) * HH + h) * (DD * DD);
#pragma unroll
    for (int nt = 0; nt < 8; nt++) {
        int col = nt * 8 + 2 * t4;
        *(float2*)(op + (wm + g) * DD + col) = make_float2(acc[nt][0], acc[nt][1]);
        *(float2*)(op + (wm + 8 + g) * DD + col) = make_float2(acc[nt][2], acc[nt][3]);
    }
}

// ---------------- K3: reduce partials, divide by exp-sum ----------------
__global__ __launch_bounds__(256) void k_ctxred() {
    int idx = blockIdx.x * 256 + threadIdx.x;
    float s = 0.f;
#pragma unroll
    for (int p = 0; p < NSPLIT; p++) s += g_ctxp[(size_t)p * (BB * HH * DD * DD) + idx];
    int d = (idx >> 6) & 63;
    int h = (idx >> 12) & 7;
    int b = idx >> 15;
    float den = 0.f;
#pragma unroll
    for (int p = 0; p < NSPLIT; p++) den += g_sump[((size_t)p * BB + b) * HID + h * 64 + d];
    g_ctx[idx] = s / den;
}

// ---------------- K4: A^T[b][hd][c] -> fp16 ----------------
__global__ __launch_bounds__(128) void k_Agemm(const float* __restrict__ wout) {
    __shared__ float Wouts[128][64];
    __shared__ float ctxs[64][64];
    int t = threadIdx.x;
    int cseg = blockIdx.x, h = blockIdx.y, b = blockIdx.z;
    int cbase = cseg * 128;
#pragma unroll
    for (int i = 0; i < 16; i++) {
        int lin4 = t + i * 128;
        int c = lin4 >> 4, e4 = lin4 & 15;
        *(float4*)&Wouts[c][e4 * 4] = *(const float4*)(wout + (size_t)(cbase + c) * HID + h * 64 + e4 * 4);
    }
    const float* ctxg = g_ctx + ((size_t)b * HH + h) * DD * DD;
#pragma unroll
    for (int i = 0; i < 8; i++) {
        int lin4 = t + i * 128;
        int d = lin4 >> 4, e4 = lin4 & 15;
        *(float4*)&ctxs[d][e4 * 4] = *(const float4*)(ctxg + d * 64 + e4 * 4);
    }
    __syncthreads();
    float acc[64];
#pragma unroll
    for (int d = 0; d < 64; d++) acc[d] = 0.f;
    for (int e = 0; e < 64; e++) {
        float w = Wouts[t][e];
#pragma unroll
        for (int d = 0; d < 64; d++) acc[d] = fmaf(w, ctxs[d][e], acc[d]);
    }
    __half* op = g_Ath + ((size_t)b * HID + h * 64) * CC + cbase + t;
    for (int d = 0; d < 64; d++) op[(size_t)d * CC] = __float2half_rn(acc[d]);
}

// ---------------- K5: fused q-softmax + output GEMM + bias + RMSNorm ----------------
__global__ __launch_bounds__(256) void k_out(const float* __restrict__ bo,
                                             const float* __restrict__ gn,
                                             float* __restrict__ y) {
    __shared__ float Qs[64][72];
    __shared__ float As[16][264];
    __shared__ float redM[4][64];
    __shared__ float redS[4][64];
    __shared__ float colM[64];
    __shared__ float colS[64];
    __shared__ float sred[64][4];
    __shared__ float cscale[64];

    int t = threadIdx.x;
    int b = blockIdx.y, n0 = blockIdx.x * 64;
    int wid = t >> 5, lane = t & 31;
    int g = lane >> 2, t4 = lane & 3;
    int wm = (wid >> 1) * 64, wn = (wid & 1) * 32;
    int part = t >> 6, col = t & 63;

    float acc[4][4][4];
#pragma unroll
    for (int mt = 0; mt < 4; mt++)
#pragma unroll
        for (int nt = 0; nt < 4; nt++)
#pragma unroll
            for (int r = 0; r < 4; r++) acc[mt][nt][r] = 0.f;

    for (int h = 0; h < 8; h++) {
        __syncthreads();
#pragma unroll
        for (int i = 0; i < 4; i++) {
            int lin4 = t + i * 256;
            int row = lin4 >> 4, c4 = (lin4 & 15) * 4;
            float qf[4];
            ld4h(g_qkvh + ((size_t)b * THID + h * 64 + row) * NN + n0 + c4, qf);
            Qs[row][c4] = qf[0]; Qs[row][c4 + 1] = qf[1];
            Qs[row][c4 + 2] = qf[2]; Qs[row][c4 + 3] = qf[3];
        }
        __syncthreads();
        float lm = -1e30f;
#pragma unroll
        for (int r = 0; r < 16; r++) lm = fmaxf(lm, Qs[part * 16 + r][col]);
        redM[part][col] = lm;
        __syncthreads();
        float M = fmaxf(fmaxf(redM[0][col], redM[1][col]), fmaxf(redM[2][col], redM[3][col]));
        float ls = 0.f;
#pragma unroll
        for (int r = 0; r < 16; r++) ls += __expf(Qs[part * 16 + r][col] - M);
        redS[part][col] = ls;
        __syncthreads();
        if (t < 64) {
            colM[t] = M;
            colS[t] = SCALE / (redS[0][t] + redS[1][t] + redS[2][t] + redS[3][t]);
        }
        __syncthreads();
#pragma unroll
        for (int i = 0; i < 16; i++) {
            int lin = t + i * 256;
            int d = lin >> 6, n = lin & 63;
            Qs[d][n] = __expf(Qs[d][n] - colM[n]) * colS[n];
        }
        for (int dc = 0; dc < 4; dc++) {
            __syncthreads();
#pragma unroll
            for (int i = 0; i < 4; i++) {
                int lin4 = t + i * 256;
                int row = lin4 >> 6, c4 = (lin4 & 63) * 4;
                float af[4];
                ld4h(g_Ath + ((size_t)b * HID + h * 64 + dc * 16 + row) * CC + c4, af);
                As[row][c4] = af[0]; As[row][c4 + 1] = af[1];
                As[row][c4 + 2] = af[2]; As[row][c4 + 3] = af[3];
            }
            __syncthreads();
#pragma unroll
            for (int kk = 0; kk < 16; kk += 8) {
                uint32_t a[4][4], bf[4][2];
#pragma unroll
                for (int mt = 0; mt < 4; mt++) {
                    int mr = wm + mt * 16 + g;
                    a[mt][0] = f2tf32(As[kk + t4][mr]);
                    a[mt][1] = f2tf32(As[kk + t4][mr + 8]);
                    a[mt][2] = f2tf32(As[kk + t4 + 4][mr]);
                    a[mt][3] = f2tf32(As[kk + t4 + 4][mr + 8]);
                }
#pragma unroll
                for (int nt = 0; nt < 4; nt++) {
                    int nc = wn + nt * 8 + g;
                    bf[nt][0] = f2tf32(Qs[dc * 16 + kk + t4][nc]);
                    bf[nt][1] = f2tf32(Qs[dc * 16 + kk + t4 + 4][nc]);
                }
#pragma unroll
                for (int mt = 0; mt < 4; mt++)
#pragma unroll
                    for (int nt = 0; nt < 4; nt++) mma_tf32(acc[mt][nt], a[mt], bf[nt]);
            }
        }
    }
    float ps[4][2];
#pragma unroll
    for (int nt = 0; nt < 4; nt++) { ps[nt][0] = 0.f; ps[nt][1] = 0.f; }
#pragma unroll
    for (int mt = 0; mt < 4; mt++) {
        int row = wm + mt * 16 + g;
        float b0v = bo[row], b1v = bo[row + 8];
#pragma unroll
        for (int nt = 0; nt < 4; nt++) {
            acc[mt][nt][0] += b0v;
            acc[mt][nt][1] += b0v;
            acc[mt][nt][2] += b1v;
            acc[mt][nt][3] += b1v;
            ps[nt][0] += acc[mt][nt][0] * acc[mt][nt][0] + acc[mt][nt][2] * acc[mt][nt][2];
            ps[nt][1] += acc[mt][nt][1] * acc[mt][nt][1] + acc[mt][nt][3] * acc[mt][nt][3];
        }
    }
#pragma unroll
    for (int nt = 0; nt < 4; nt++)
#pragma unroll
        for (int j = 0; j < 2; j++) {
#pragma unroll
            for (int o = 4; o <= 16; o <<= 1)
                ps[nt][j] += __shfl_xor_sync(0xffffffffu, ps[nt][j], o);
        }
    if (g == 0) {
#pragma unroll
        for (int nt = 0; nt < 4; nt++)
#pragma unroll
            for (int j = 0; j < 2; j++)
                sred[wn + nt * 8 + 2 * t4 + j][wid >> 1] = ps[nt][j];
    }
    __syncthreads();
    if (t < 64) {
        float tot = sred[t][0] + sred[t][1] + sred[t][2] + sred[t][3];
        cscale[t] = SQRTC / fmaxf(sqrtf(tot), 1e-12f);
    }
    __syncthreads();
#pragma unroll
    for (int mt = 0; mt < 4; mt++) {
        int row = wm + mt * 16 + g;
        float g0 = gn[row], g1 = gn[row + 8];
#pragma unroll
        for (int nt = 0; nt < 4; nt++) {
            int c = wn + nt * 8 + 2 * t4;
            float s0 = cscale[c], s1 = cscale[c + 1];
            *(float2*)(y + ((size_t)b * CC + row) * NN + n0 + c) =
                make_float2(acc[mt][nt][0] * s0 * g0, acc[mt][nt][1] * s1 * g0);
            *(float2*)(y + ((size_t)b * CC + row + 8) * NN + n0 + c) =
                make_float2(acc[mt][nt][2] * s0 * g1, acc[mt][nt][3] * s1 * g1);
        }
    }
}

// ---------------- launch ----------------
extern "C" void kernel_launch(void* const* d_in, const int* in_sizes, int n_in,
                              void* d_out, int out_size) {
    const float* x      = (const float*)d_in[0];
    const float* w_qkv  = (const float*)d_in[1];
    const float* w_out  = (const float*)d_in[2];
    const float* b_out  = (const float*)d_in[3];
    const float* g_norm = (const float*)d_in[4];
    float* y = (float*)d_out;

    k_wt<<<dim3(CC / 32, THID / 32), dim3(32, 8)>>>(w_qkv);
    k_qkv<<<dim3(NN / 128, THID / 128, BB), 256>>>(x);
    k_context<<<dim3(NSPLIT, HH, BB), 128>>>();
    k_ctxred<<<(BB * HH * DD * DD) / 256, 256>>>();
    k_Agemm<<<dim3(2, HH, BB), 128>>>(w_out);
    k_out<<<dim3(NN / 64, BB), 256>>>(b_out, g_norm, y);
}